// round 15
// baseline (speedup 1.0000x reference)
#include <cuda_runtime.h>
#include <cuda_bf16.h>
#include <cstdint>

#define B_ 2
#define T_ 2048
#define D_ 1024
#define NT (B_*T_)          // 4096
#define NH 16
#define DH 64
#define AMAX 15
#define NEGF (-1e30f)
#define CH 16               // scan chunks
#define CL (T_/CH)          // 128
#define LOG2_095 (-0.07400058003f)   // log2(0.95)
#define P128 (0.0014080610f)         // 0.95^128

// ---------------- scratch (device-side only; NEVER passed from host) ---------
__device__ float g_gates[NT*9];
__device__ float g_kick[NT*3];
__device__ float g_Ilocal[(size_t)NT*D_];
__device__ float g_cend[B_*CH*D_];
__device__ float g_cin[B_*CH*D_];
__device__ __nv_bfloat16 g_Abh[(size_t)3*NT*3*D_];  // A hi, all 3 projections (also attn-out)
__device__ __nv_bfloat16 g_Abl[(size_t)3*NT*3*D_];  // A lo
__device__ __nv_bfloat16 g_Bbh[(size_t)3*D_*3*D_];  // B hi, all 3 projections (also o_w)
__device__ __nv_bfloat16 g_Bbl[(size_t)3*D_*3*D_];  // B lo
__device__ float g_qkv[(size_t)3*NT*D_];            // q,k,v

// ---------------- PTX helpers ------------------------------------------------
__device__ __forceinline__ uint32_t cvta_smem(const void* p){
    uint32_t a;
    asm("{ .reg .u64 t; cvta.to.shared.u64 t, %1; cvt.u32.u64 %0, t; }":"=r"(a):"l"(p));
    return a;
}
__device__ __forceinline__ void cpasync16(uint32_t dst, const void* src){
    asm volatile("cp.async.cg.shared.global [%0],[%1],16;"::"r"(dst),"l"(src));
}
__device__ __forceinline__ void cp_commit(){ asm volatile("cp.async.commit_group;":::"memory"); }
template<int N> __device__ __forceinline__ void cp_wait(){
    asm volatile("cp.async.wait_group %0;"::"n"(N):"memory");
}
#define LDSM4(r0,r1,r2,r3,addr) \
    asm volatile("ldmatrix.sync.aligned.m8n8.x4.shared.b16 {%0,%1,%2,%3}, [%4];" \
        : "=r"(r0),"=r"(r1),"=r"(r2),"=r"(r3) : "r"(addr))
#define LDSM2(r0,r1,addr) \
    asm volatile("ldmatrix.sync.aligned.m8n8.x2.shared.b16 {%0,%1}, [%2];" \
        : "=r"(r0),"=r"(r1) : "r"(addr))
#define MMA16816(c0,c1,c2,c3,a0,a1,a2,a3,b0,b1) \
    asm volatile("mma.sync.aligned.m16n8k16.row.col.f32.bf16.bf16.f32 " \
        "{%0,%1,%2,%3}, {%4,%5,%6,%7}, {%8,%9}, {%0,%1,%2,%3};" \
        : "+f"(c0),"+f"(c1),"+f"(c2),"+f"(c3) \
        : "r"(a0),"r"(a1),"r"(a2),"r"(a3),"r"(b0),"r"(b1))
// 3-term split product: ah*bh + ah*bl + al*bh
#define MMA3(c, ah_, al_, bh_, bl_) do { \
    MMA16816(c.x,c.y,c.z,c.w, ah_.x,ah_.y,ah_.z,ah_.w, bh_.x,bh_.y); \
    MMA16816(c.x,c.y,c.z,c.w, ah_.x,ah_.y,ah_.z,ah_.w, bl_.x,bl_.y); \
    MMA16816(c.x,c.y,c.z,c.w, al_.x,al_.y,al_.z,al_.w, bh_.x,bh_.y); \
} while(0)

// ---------------- 1) per-token stats -----------------------------------------
__global__ void k_stats(const float* __restrict__ x,
                        const float* __restrict__ gate_w,
                        const float* __restrict__ gate_b,
                        const float* __restrict__ kick_w,
                        const float* __restrict__ kick_b) {
    int n = blockIdx.x;
    int t = n % T_;
    int tid = threadIdx.x;
    const float* xr = x + (size_t)n * D_;
    const float* xp = xr - D_;

    float s[15];
    #pragma unroll
    for (int i = 0; i < 15; i++) s[i] = 0.f;
    for (int d = tid; d < D_; d += 256) {
        float xv = xr[d];
        float pv = (t > 0) ? xp[d] : 0.f;
        s[0] += xv * xv; s[1] += pv * pv; s[2] += xv * pv;
        #pragma unroll
        for (int j = 0; j < 9; j++) s[3 + j] += xv * gate_w[j * D_ + d];
        #pragma unroll
        for (int p = 0; p < 3; p++) s[12 + p] += xv * kick_w[p * D_ + d];
    }
    #pragma unroll
    for (int i = 0; i < 15; i++)
        for (int off = 16; off; off >>= 1) s[i] += __shfl_xor_sync(~0u, s[i], off);

    __shared__ float red[8][15];
    int w = tid >> 5, l = tid & 31;
    if (l == 0) {
        #pragma unroll
        for (int i = 0; i < 15; i++) red[w][i] = s[i];
    }
    __syncthreads();
    if (tid == 0) {
        float f[15];
        #pragma unroll
        for (int i = 0; i < 15; i++) {
            float a = 0.f;
            #pragma unroll
            for (int w2 = 0; w2 < 8; w2++) a += red[w2][i];
            f[i] = a;
        }
        float n1 = fmaxf(sqrtf(f[0]), 1e-12f);
        float n2 = fmaxf(sqrtf(f[1]), 1e-12f);
        float cosv = (t > 0) ? f[2] / (n1 * n2) : 0.f;
        float stag = (cosv > 0.95f) ? 1.f : 0.f;
        #pragma unroll
        for (int p = 0; p < 3; p++) {
            float l0 = f[3+p*3+0] + gate_b[p*3+0];
            float l1 = f[3+p*3+1] + gate_b[p*3+1];
            float l2 = f[3+p*3+2] + gate_b[p*3+2];
            float m = fmaxf(l0, fmaxf(l1, l2));
            float e0 = expf(l0-m), e1 = expf(l1-m), e2 = expf(l2-m);
            float inv = 1.f / (e0+e1+e2);
            float g0 = fminf(e0*inv, 0.6f);
            float g1 = fmaxf(fminf(e1*inv, 0.6f), 0.25f);
            float g2 = fminf(e2*inv, 0.6f);
            float inv2 = 1.f / (g0+g1+g2);
            g_gates[n*9+p*3+0] = g0*inv2;
            g_gates[n*9+p*3+1] = g1*inv2;
            g_gates[n*9+p*3+2] = g2*inv2;
            float ks = 1.f / (1.f + expf(-(f[12+p] + kick_b[p])));
            g_kick[n*3+p] = stag * ks;
        }
    }
}

// ---------------- 2) chunked EMA scan ----------------------------------------
__global__ void k_scan1(const float* __restrict__ x) {
    int d = blockIdx.x * 256 + threadIdx.x;
    int c = blockIdx.y, b = blockIdx.z;
    const float* xb = x + ((size_t)(b*T_ + c*CL))*D_ + d;
    float* Ib = g_Ilocal + ((size_t)(b*T_ + c*CL))*D_ + d;
    float L; int t0;
    if (c == 0) { L = xb[0]; Ib[0] = L; t0 = 1; }
    else { L = 0.f; t0 = 0; }
    for (int t = t0; t < CL; t++) {
        L = 0.95f*L + 0.05f*xb[(size_t)t*D_];
        Ib[(size_t)t*D_] = L;
    }
    g_cend[(b*CH + c)*D_ + d] = L;
}

__global__ void k_scan2() {
    int d = blockIdx.x * 256 + threadIdx.x;
    int b = blockIdx.y;
    float I = g_cend[(b*CH + 0)*D_ + d];
    g_cin[(b*CH + 0)*D_ + d] = 0.f;
    for (int c = 1; c < CH; c++) {
        g_cin[(b*CH + c)*D_ + d] = I;
        I = g_cend[(b*CH + c)*D_ + d] + P128 * I;
    }
}

// ---------------- 3) split-bf16 operand builders ------------------------------
__device__ __forceinline__ void split_bf(float v, __nv_bfloat16* H, __nv_bfloat16* L, size_t i){
    __nv_bfloat16 h = __float2bfloat16_rn(v);
    H[i] = h;
    L[i] = __float2bfloat16_rn(v - __bfloat162float(h));
}

// A'' for ALL projections: [p][n][ g0*x | g1*I | g2*(dx + kick*kick_v) ]
__global__ void k_buildA(const float* __restrict__ x, const float* __restrict__ kick_v) {
    int n = blockIdx.x;
    int b = n / T_, t = n % T_;
    int c = t / CL;
    float pfac = exp2f((float)((t % CL) + 1) * LOG2_095);   // 0.95^(tm+1)
    __shared__ float gg[9], kk[3];
    if (threadIdx.x < 9) gg[threadIdx.x] = g_gates[n*9 + threadIdx.x];
    if (threadIdx.x < 3) kk[threadIdx.x] = g_kick[n*3 + threadIdx.x];
    __syncthreads();
    for (int d = threadIdx.x; d < D_; d += 256) {
        float xv = x[(size_t)n*D_ + d];
        float dv = (t > 0) ? (xv - x[(size_t)(n-1)*D_ + d]) : 0.f;
        float Iv = g_Ilocal[(size_t)n*D_ + d] + pfac * g_cin[(b*CH + c)*D_ + d];
        #pragma unroll
        for (int p = 0; p < 3; p++) {
            size_t base = ((size_t)p*NT + n) * (3*D_);
            split_bf(gg[p*3+0]*xv, g_Abh, g_Abl, base + d);
            split_bf(gg[p*3+1]*Iv, g_Abh, g_Abl, base + D_ + d);
            split_bf(gg[p*3+2]*(dv + kk[p]*kick_v[p*D_ + d]), g_Abh, g_Abl, base + 2*D_ + d);
        }
    }
}

// B'' for ALL projections: global row (p*1024+o) = [ Wp_p[o] | Wi_p[o] | Wd_p[o] ]
__global__ void k_buildB(const float* __restrict__ Wp, const float* __restrict__ Wi,
                         const float* __restrict__ Wd) {
    int row = blockIdx.x;                    // 0..3*D_-1
    size_t base = (size_t)row * (3*D_);
    size_t wsrc = (size_t)row * D_;
    for (int d = threadIdx.x; d < D_; d += 256) {
        split_bf(Wp[wsrc + d], g_Bbh, g_Bbl, base + d);
        split_bf(Wi[wsrc + d], g_Bbh, g_Bbl, base + D_ + d);
        split_bf(Wd[wsrc + d], g_Bbh, g_Bbl, base + 2*D_ + d);
    }
}

// split o_w into the start of the B buffers (after projection GEMMs are done)
__global__ void k_split_ow(const float* __restrict__ src, int nElem) {
    int i = blockIdx.x * 256 + threadIdx.x;
    if (i < nElem) split_bf(src[i], g_Bbh, g_Bbl, i);
}

// ---------------- 4) bf16 mma.sync GEMM — 128x128 tile, 3-stage pipeline -----
// 8 warps (4x2), warp tile 32x64. C = Ah*Bh^T + Ah*Bl^T + Al*Bh^T, fp32 acc.
// blockIdx.z = projection p: A base = p*NT*K, B base = p*D_*K; ldc = 1024.
#define BKq 32
#define APADq 40                        // 80 B rows: conflict-free ldmatrix banking
#define A_EL (128*APADq)                // 5120 elems (A: 128 rows)
#define B_EL (128*APADq)                // 5120 elems (B: 128 rows)
#define STG (2*A_EL + 2*B_EL)           // 20480 elems (40960 B) per stage
#define GEMM_SMEM (3*STG*2)             // 122880 B, 3 stages

#define LOADSTAGE(st, ko) do { \
    uint32_t so_ = (uint32_t)(st) * STG; \
    cpasync16(smb + (so_ + sA0)*2u,  pAh0 + (ko)); \
    cpasync16(smb + (so_ + sA1)*2u,  pAh1 + (ko)); \
    cpasync16(smb + (so_ + sAl0)*2u, pAl0 + (ko)); \
    cpasync16(smb + (so_ + sAl1)*2u, pAl1 + (ko)); \
    cpasync16(smb + (so_ + sB0)*2u,  pBh0 + (ko)); \
    cpasync16(smb + (so_ + sB1)*2u,  pBh1 + (ko)); \
    cpasync16(smb + (so_ + sBl0)*2u, pBl0 + (ko)); \
    cpasync16(smb + (so_ + sBl1)*2u, pBl1 + (ko)); \
    cp_commit(); \
} while(0)

__global__ void __launch_bounds__(256,1) k_gemm(float* __restrict__ Cext,
                                                int K, int useExt)
{
    int z = blockIdx.z;
    const __nv_bfloat16* Ah = g_Abh + (size_t)z*NT*K;
    const __nv_bfloat16* Al = g_Abl + (size_t)z*NT*K;
    const __nv_bfloat16* Bh = g_Bbh + (size_t)z*D_*K;
    const __nv_bfloat16* Bl = g_Bbl + (size_t)z*D_*K;
    float* C = useExt ? Cext : (g_qkv + (size_t)z*NT*D_);

    extern __shared__ __align__(16) __nv_bfloat16 smarr[];
    uint32_t smb = cvta_smem(smarr);
    int tid = threadIdx.x, lane = tid & 31, wid = tid >> 5;
    int warp_m = wid >> 1, warp_n = wid & 1;      // 4 x 2 warps; warp tile 32x64
    int n0 = blockIdx.x * 128;
    int m0 = blockIdx.y * 128;

    float4 acc[2][8];
    #pragma unroll
    for (int mi = 0; mi < 2; mi++)
        #pragma unroll
        for (int ni = 0; ni < 8; ni++) acc[mi][ni] = make_float4(0.f,0.f,0.f,0.f);

    // loader mapping: 8 cp.async per thread per stage
    int lr = tid >> 2;                  // 0..63
    int u  = (tid & 3) * 8;             // elem offset 0,8,16,24

    const __nv_bfloat16* pAh0 = Ah + (size_t)(m0 + lr)*K + u;
    const __nv_bfloat16* pAh1 = Ah + (size_t)(m0 + lr + 64)*K + u;
    const __nv_bfloat16* pAl0 = Al + (size_t)(m0 + lr)*K + u;
    const __nv_bfloat16* pAl1 = Al + (size_t)(m0 + lr + 64)*K + u;
    const __nv_bfloat16* pBh0 = Bh + (size_t)(n0 + lr)*K + u;
    const __nv_bfloat16* pBh1 = Bh + (size_t)(n0 + lr + 64)*K + u;
    const __nv_bfloat16* pBl0 = Bl + (size_t)(n0 + lr)*K + u;
    const __nv_bfloat16* pBl1 = Bl + (size_t)(n0 + lr + 64)*K + u;
    uint32_t sA0  = (uint32_t)(lr*APADq + u);
    uint32_t sA1  = (uint32_t)((lr+64)*APADq + u);
    uint32_t sAl0 = A_EL + sA0;
    uint32_t sAl1 = A_EL + sA1;
    uint32_t sB0  = 2*A_EL + sA0;
    uint32_t sB1  = 2*A_EL + sA1;
    uint32_t sBl0 = sB0 + B_EL;
    uint32_t sBl1 = sB1 + B_EL;

    int NKB = K / BKq;

    LOADSTAGE(0, 0);
    LOADSTAGE(1, BKq);

    // ldmatrix lane addressing
    int arow = warp_m*32 + (lane & 15);
    int acol = (lane >> 4) * 8;
    int brow = warp_n*64 + (lane & 7);
    int bcol = ((lane >> 3) & 1) * 8;

    for (int kb = 0; kb < NKB; kb++) {
        if (kb + 1 < NKB) cp_wait<1>(); else cp_wait<0>();
        __syncthreads();
        if (kb + 2 < NKB) LOADSTAGE((kb + 2) % 3, (kb + 2) * BKq);

        uint32_t base = smb + (uint32_t)((kb % 3) * STG) * 2u;
        uint32_t aH = base;
        uint32_t aL = base + A_EL*2u;
        uint32_t bH = base + 2*A_EL*2u;
        uint32_t bL = bH + B_EL*2u;

        #pragma unroll
        for (int ks = 0; ks < 2; ks++) {
            uint4 ah[2], al[2];
            uint2 bh[8], bl[8];
            #pragma unroll
            for (int mi = 0; mi < 2; mi++) {
                uint32_t off = (uint32_t)((arow + mi*16)*APADq + acol + ks*16) * 2u;
                LDSM4(ah[mi].x, ah[mi].y, ah[mi].z, ah[mi].w, aH + off);
                LDSM4(al[mi].x, al[mi].y, al[mi].z, al[mi].w, aL + off);
            }
            #pragma unroll
            for (int ni = 0; ni < 8; ni++) {
                uint32_t off = (uint32_t)((brow + ni*8)*APADq + bcol + ks*16) * 2u;
                LDSM2(bh[ni].x, bh[ni].y, bH + off);
                LDSM2(bl[ni].x, bl[ni].y, bL + off);
            }
            #pragma unroll
            for (int mi = 0; mi < 2; mi++)
                #pragma unroll
                for (int ni = 0; ni < 8; ni++)
                    MMA3(acc[mi][ni], ah[mi], al[mi], bh[ni], bl[ni]);
        }
        __syncthreads();
    }

    #pragma unroll
    for (int mi = 0; mi < 2; mi++) {
        int r0 = m0 + warp_m*32 + mi*16 + (lane >> 2);
        #pragma unroll
        for (int ni = 0; ni < 8; ni++) {
            int cc = n0 + warp_n*64 + ni*8 + (lane & 3)*2;
            *(float2*)(C + (size_t)r0*1024 + cc)     = make_float2(acc[mi][ni].x, acc[mi][ni].y);
            *(float2*)(C + (size_t)(r0+8)*1024 + cc) = make_float2(acc[mi][ni].z, acc[mi][ni].w);
        }
    }
}

// ---------------- 5) sparse dilated attention (writes split-bf16 out) --------
__global__ void k_attn(const int* __restrict__ positions, int adim) {
    const float* gq = g_qkv;
    const float* gk = g_qkv + (size_t)NT*D_;
    const float* gv = g_qkv + (size_t)2*NT*D_;
    int n = blockIdx.x;
    int b = n / T_, t = n % T_;
    int h = threadIdx.x >> 5;
    int lane = threadIdx.x & 31;

    int cnt = 1 + min(t, 3);
    for (int kk = 4; kk <= t; kk <<= 1) cnt++;

    const float* qr = gq + (size_t)n*D_ + h*DH;
    float2 qv = *(const float2*)(qr + lane*2);

    int pos[AMAX];
    float sc[AMAX];
    #pragma unroll
    for (int a = 0; a < AMAX; a++) {
        if (a < cnt) {
            pos[a] = positions[t*adim + a];
            const float* kr = gk + (size_t)(b*T_ + pos[a])*D_ + h*DH;
            float2 kv = *(const float2*)(kr + lane*2);
            float s = qv.x*kv.x + qv.y*kv.y;
            #pragma unroll
            for (int off = 16; off; off >>= 1) s += __shfl_xor_sync(~0u, s, off);
            sc[a] = s * 0.125f;
        } else { pos[a] = 0; sc[a] = NEGF; }
    }
    float m = NEGF;
    #pragma unroll
    for (int a = 0; a < AMAX; a++) m = fmaxf(m, sc[a]);
    float sum = 0.f;
    #pragma unroll
    for (int a = 0; a < AMAX; a++) {
        sc[a] = (a < cnt) ? expf(sc[a] - m) : 0.f;
        sum += sc[a];
    }
    float inv = 1.f / sum;
    float2 acc = make_float2(0.f, 0.f);
    #pragma unroll
    for (int a = 0; a < AMAX; a++) {
        if (a < cnt) {
            const float* vr = gv + (size_t)(b*T_ + pos[a])*D_ + h*DH;
            float2 vv = *(const float2*)(vr + lane*2);
            float w = sc[a]*inv;
            acc.x += w*vv.x; acc.y += w*vv.y;
        }
    }
    size_t oidx = (size_t)n*D_ + h*DH + lane*2;
    split_bf(acc.x, g_Abh, g_Abl, oidx);
    split_bf(acc.y, g_Abh, g_Abl, oidx + 1);
}

// ---------------- launch ------------------------------------------------------
// Only harness pointers and plain ints cross the host->kernel boundary.
extern "C" void kernel_launch(void* const* d_in, const int* in_sizes, int n_in,
                              void* d_out, int out_size) {
    const float* x      = (const float*)d_in[0];
    const float* Wp     = (const float*)d_in[1];
    const float* Wi     = (const float*)d_in[2];
    const float* Wd     = (const float*)d_in[3];
    const float* gate_w = (const float*)d_in[4];
    const float* gate_b = (const float*)d_in[5];
    const float* kick_v = (const float*)d_in[6];
    const float* kick_w = (const float*)d_in[7];
    const float* kick_b = (const float*)d_in[8];
    const float* o_w    = (const float*)d_in[9];
    const int* positions = (const int*)d_in[10];
    int adim = in_sizes[10] / T_;

    cudaFuncSetAttribute(k_gemm, cudaFuncAttributeMaxDynamicSharedMemorySize, GEMM_SMEM);

    k_stats<<<NT, 256>>>(x, gate_w, gate_b, kick_w, kick_b);
    k_scan1<<<dim3(D_/256, CH, B_), 256>>>(x);
    k_scan2<<<dim3(D_/256, B_), 256>>>();

    k_buildA<<<NT, 256>>>(x, kick_v);              // all 3 projections
    k_buildB<<<3*D_, 256>>>(Wp, Wi, Wd);           // all 3 projections

    // q,k,v: one batched GEMM, gridDim.z = projection (M=4096, N=1024, K'=3072)
    k_gemm<<<dim3(D_/128, NT/128, 3), 256, GEMM_SMEM>>>(nullptr, 3*D_, 0);

    k_attn<<<NT, 512>>>(positions, adim);          // writes split-bf16 into g_Ab*
    k_split_ow<<<(D_*D_)/256, 256>>>(o_w, D_*D_);

    // out = attn @ o_w^T  (M=4096, N=1024, K=1024)
    k_gemm<<<dim3(D_/128, NT/128, 1), 256, GEMM_SMEM>>>((float*)d_out, D_, 1);
}

// round 16
// speedup vs baseline: 1.0648x; 1.0648x over previous
#include <cuda_runtime.h>
#include <cuda_bf16.h>
#include <cstdint>

#define B_ 2
#define T_ 2048
#define D_ 1024
#define NT (B_*T_)          // 4096
#define NH 16
#define DH 64
#define AMAX 15
#define NEGF (-1e30f)
#define CH 16               // scan chunks
#define CL (T_/CH)          // 128
#define LOG2_095 (-0.07400058003f)   // log2(0.95)
#define P128 (0.0014080610f)         // 0.95^128

// ---------------- scratch (device-side only; NEVER passed from host) ---------
__device__ float g_gates[NT*9];
__device__ float g_kick[NT*3];
__device__ float g_Ilocal[(size_t)NT*D_];
__device__ float g_cend[B_*CH*D_];
__device__ float g_cin[B_*CH*D_];
__device__ __nv_bfloat16 g_Abh[(size_t)3*NT*3*D_];  // A hi, all 3 projections (also attn-out)
__device__ __nv_bfloat16 g_Abl[(size_t)3*NT*3*D_];  // A lo
__device__ __nv_bfloat16 g_Bbh[(size_t)3*D_*3*D_];  // B hi, all 3 projections (also o_w)
__device__ __nv_bfloat16 g_Bbl[(size_t)3*D_*3*D_];  // B lo
__device__ float g_qkv[(size_t)3*NT*D_];            // q,k,v

// ---------------- PTX helpers ------------------------------------------------
__device__ __forceinline__ uint32_t cvta_smem(const void* p){
    uint32_t a;
    asm("{ .reg .u64 t; cvta.to.shared.u64 t, %1; cvt.u32.u64 %0, t; }":"=r"(a):"l"(p));
    return a;
}
__device__ __forceinline__ void cpasync16(uint32_t dst, const void* src){
    asm volatile("cp.async.cg.shared.global [%0],[%1],16;"::"r"(dst),"l"(src));
}
__device__ __forceinline__ void cp_commit(){ asm volatile("cp.async.commit_group;":::"memory"); }
template<int N> __device__ __forceinline__ void cp_wait(){
    asm volatile("cp.async.wait_group %0;"::"n"(N):"memory");
}
#define LDSM4(r0,r1,r2,r3,addr) \
    asm volatile("ldmatrix.sync.aligned.m8n8.x4.shared.b16 {%0,%1,%2,%3}, [%4];" \
        : "=r"(r0),"=r"(r1),"=r"(r2),"=r"(r3) : "r"(addr))
#define LDSM2(r0,r1,addr) \
    asm volatile("ldmatrix.sync.aligned.m8n8.x2.shared.b16 {%0,%1}, [%2];" \
        : "=r"(r0),"=r"(r1) : "r"(addr))
#define MMA16816(c0,c1,c2,c3,a0,a1,a2,a3,b0,b1) \
    asm volatile("mma.sync.aligned.m16n8k16.row.col.f32.bf16.bf16.f32 " \
        "{%0,%1,%2,%3}, {%4,%5,%6,%7}, {%8,%9}, {%0,%1,%2,%3};" \
        : "+f"(c0),"+f"(c1),"+f"(c2),"+f"(c3) \
        : "r"(a0),"r"(a1),"r"(a2),"r"(a3),"r"(b0),"r"(b1))
// 3-term split product: ah*bh + ah*bl + al*bh
#define MMA3(c, ah_, al_, bh_, bl_) do { \
    MMA16816(c.x,c.y,c.z,c.w, ah_.x,ah_.y,ah_.z,ah_.w, bh_.x,bh_.y); \
    MMA16816(c.x,c.y,c.z,c.w, ah_.x,ah_.y,ah_.z,ah_.w, bl_.x,bl_.y); \
    MMA16816(c.x,c.y,c.z,c.w, al_.x,al_.y,al_.z,al_.w, bh_.x,bh_.y); \
} while(0)

// ---------------- 1) per-token stats -----------------------------------------
__global__ void k_stats(const float* __restrict__ x,
                        const float* __restrict__ gate_w,
                        const float* __restrict__ gate_b,
                        const float* __restrict__ kick_w,
                        const float* __restrict__ kick_b) {
    int n = blockIdx.x;
    int t = n % T_;
    int tid = threadIdx.x;
    const float* xr = x + (size_t)n * D_;
    const float* xp = xr - D_;

    float s[15];
    #pragma unroll
    for (int i = 0; i < 15; i++) s[i] = 0.f;
    for (int d = tid; d < D_; d += 256) {
        float xv = xr[d];
        float pv = (t > 0) ? xp[d] : 0.f;
        s[0] += xv * xv; s[1] += pv * pv; s[2] += xv * pv;
        #pragma unroll
        for (int j = 0; j < 9; j++) s[3 + j] += xv * gate_w[j * D_ + d];
        #pragma unroll
        for (int p = 0; p < 3; p++) s[12 + p] += xv * kick_w[p * D_ + d];
    }
    #pragma unroll
    for (int i = 0; i < 15; i++)
        for (int off = 16; off; off >>= 1) s[i] += __shfl_xor_sync(~0u, s[i], off);

    __shared__ float red[8][15];
    int w = tid >> 5, l = tid & 31;
    if (l == 0) {
        #pragma unroll
        for (int i = 0; i < 15; i++) red[w][i] = s[i];
    }
    __syncthreads();
    if (tid == 0) {
        float f[15];
        #pragma unroll
        for (int i = 0; i < 15; i++) {
            float a = 0.f;
            #pragma unroll
            for (int w2 = 0; w2 < 8; w2++) a += red[w2][i];
            f[i] = a;
        }
        float n1 = fmaxf(sqrtf(f[0]), 1e-12f);
        float n2 = fmaxf(sqrtf(f[1]), 1e-12f);
        float cosv = (t > 0) ? f[2] / (n1 * n2) : 0.f;
        float stag = (cosv > 0.95f) ? 1.f : 0.f;
        #pragma unroll
        for (int p = 0; p < 3; p++) {
            float l0 = f[3+p*3+0] + gate_b[p*3+0];
            float l1 = f[3+p*3+1] + gate_b[p*3+1];
            float l2 = f[3+p*3+2] + gate_b[p*3+2];
            float m = fmaxf(l0, fmaxf(l1, l2));
            float e0 = expf(l0-m), e1 = expf(l1-m), e2 = expf(l2-m);
            float inv = 1.f / (e0+e1+e2);
            float g0 = fminf(e0*inv, 0.6f);
            float g1 = fmaxf(fminf(e1*inv, 0.6f), 0.25f);
            float g2 = fminf(e2*inv, 0.6f);
            float inv2 = 1.f / (g0+g1+g2);
            g_gates[n*9+p*3+0] = g0*inv2;
            g_gates[n*9+p*3+1] = g1*inv2;
            g_gates[n*9+p*3+2] = g2*inv2;
            float ks = 1.f / (1.f + expf(-(f[12+p] + kick_b[p])));
            g_kick[n*3+p] = stag * ks;
        }
    }
}

// ---------------- 2) chunked EMA scan ----------------------------------------
__global__ void k_scan1(const float* __restrict__ x) {
    int d = blockIdx.x * 256 + threadIdx.x;
    int c = blockIdx.y, b = blockIdx.z;
    const float* xb = x + ((size_t)(b*T_ + c*CL))*D_ + d;
    float* Ib = g_Ilocal + ((size_t)(b*T_ + c*CL))*D_ + d;
    float L; int t0;
    if (c == 0) { L = xb[0]; Ib[0] = L; t0 = 1; }
    else { L = 0.f; t0 = 0; }
    for (int t = t0; t < CL; t++) {
        L = 0.95f*L + 0.05f*xb[(size_t)t*D_];
        Ib[(size_t)t*D_] = L;
    }
    g_cend[(b*CH + c)*D_ + d] = L;
}

__global__ void k_scan2() {
    int d = blockIdx.x * 256 + threadIdx.x;
    int b = blockIdx.y;
    float I = g_cend[(b*CH + 0)*D_ + d];
    g_cin[(b*CH + 0)*D_ + d] = 0.f;
    for (int c = 1; c < CH; c++) {
        g_cin[(b*CH + c)*D_ + d] = I;
        I = g_cend[(b*CH + c)*D_ + d] + P128 * I;
    }
}

// ---------------- 3) split-bf16 operand builders ------------------------------
__device__ __forceinline__ void split_bf(float v, __nv_bfloat16* H, __nv_bfloat16* L, size_t i){
    __nv_bfloat16 h = __float2bfloat16_rn(v);
    H[i] = h;
    L[i] = __float2bfloat16_rn(v - __bfloat162float(h));
}

// A'' for ALL projections: [p][n][ g0*x | g1*I | g2*(dx + kick*kick_v) ]
__global__ void k_buildA(const float* __restrict__ x, const float* __restrict__ kick_v) {
    int n = blockIdx.x;
    int b = n / T_, t = n % T_;
    int c = t / CL;
    float pfac = exp2f((float)((t % CL) + 1) * LOG2_095);   // 0.95^(tm+1)
    __shared__ float gg[9], kk[3];
    if (threadIdx.x < 9) gg[threadIdx.x] = g_gates[n*9 + threadIdx.x];
    if (threadIdx.x < 3) kk[threadIdx.x] = g_kick[n*3 + threadIdx.x];
    __syncthreads();
    for (int d = threadIdx.x; d < D_; d += 256) {
        float xv = x[(size_t)n*D_ + d];
        float dv = (t > 0) ? (xv - x[(size_t)(n-1)*D_ + d]) : 0.f;
        float Iv = g_Ilocal[(size_t)n*D_ + d] + pfac * g_cin[(b*CH + c)*D_ + d];
        #pragma unroll
        for (int p = 0; p < 3; p++) {
            size_t base = ((size_t)p*NT + n) * (3*D_);
            split_bf(gg[p*3+0]*xv, g_Abh, g_Abl, base + d);
            split_bf(gg[p*3+1]*Iv, g_Abh, g_Abl, base + D_ + d);
            split_bf(gg[p*3+2]*(dv + kk[p]*kick_v[p*D_ + d]), g_Abh, g_Abl, base + 2*D_ + d);
        }
    }
}

// B'' for ALL projections: global row (p*1024+o) = [ Wp_p[o] | Wi_p[o] | Wd_p[o] ]
__global__ void k_buildB(const float* __restrict__ Wp, const float* __restrict__ Wi,
                         const float* __restrict__ Wd) {
    int row = blockIdx.x;                    // 0..3*D_-1
    size_t base = (size_t)row * (3*D_);
    size_t wsrc = (size_t)row * D_;
    for (int d = threadIdx.x; d < D_; d += 256) {
        split_bf(Wp[wsrc + d], g_Bbh, g_Bbl, base + d);
        split_bf(Wi[wsrc + d], g_Bbh, g_Bbl, base + D_ + d);
        split_bf(Wd[wsrc + d], g_Bbh, g_Bbl, base + 2*D_ + d);
    }
}

// split o_w into the start of the B buffers (after projection GEMMs are done)
__global__ void k_split_ow(const float* __restrict__ src, int nElem) {
    int i = blockIdx.x * 256 + threadIdx.x;
    if (i < nElem) split_bf(src[i], g_Bbh, g_Bbl, i);
}

// ---------------- 4) bf16 mma.sync GEMM — 128x128 tile, 2-stage, 2 CTA/SM ----
// 8 warps (4x2), warp tile 32x64. C = Ah*Bh^T + Ah*Bl^T + Al*Bh^T, fp32 acc.
// blockIdx.z = projection p: A base = p*NT*K, B base = p*D_*K; ldc = 1024.
#define BKq 32
#define APADq 40                        // 80 B rows: conflict-free ldmatrix banking
#define A_EL (128*APADq)                // 5120 elems (A: 128 rows)
#define B_EL (128*APADq)                // 5120 elems (B: 128 rows)
#define STG (2*A_EL + 2*B_EL)           // 20480 elems (40960 B) per stage
#define GEMM_SMEM (2*STG*2)             // 81920 B, 2 stages → 2 CTAs/SM

#define LOADSTAGE(st, ko) do { \
    uint32_t so_ = (uint32_t)(st) * STG; \
    cpasync16(smb + (so_ + sA0)*2u,  pAh0 + (ko)); \
    cpasync16(smb + (so_ + sA1)*2u,  pAh1 + (ko)); \
    cpasync16(smb + (so_ + sAl0)*2u, pAl0 + (ko)); \
    cpasync16(smb + (so_ + sAl1)*2u, pAl1 + (ko)); \
    cpasync16(smb + (so_ + sB0)*2u,  pBh0 + (ko)); \
    cpasync16(smb + (so_ + sB1)*2u,  pBh1 + (ko)); \
    cpasync16(smb + (so_ + sBl0)*2u, pBl0 + (ko)); \
    cpasync16(smb + (so_ + sBl1)*2u, pBl1 + (ko)); \
    cp_commit(); \
} while(0)

__global__ void __launch_bounds__(256,2) k_gemm(float* __restrict__ Cext,
                                                int K, int useExt)
{
    int z = blockIdx.z;
    const __nv_bfloat16* Ah = g_Abh + (size_t)z*NT*K;
    const __nv_bfloat16* Al = g_Abl + (size_t)z*NT*K;
    const __nv_bfloat16* Bh = g_Bbh + (size_t)z*D_*K;
    const __nv_bfloat16* Bl = g_Bbl + (size_t)z*D_*K;
    float* C = useExt ? Cext : (g_qkv + (size_t)z*NT*D_);

    extern __shared__ __align__(16) __nv_bfloat16 smarr[];
    uint32_t smb = cvta_smem(smarr);
    int tid = threadIdx.x, lane = tid & 31, wid = tid >> 5;
    int warp_m = wid >> 1, warp_n = wid & 1;      // 4 x 2 warps; warp tile 32x64
    int n0 = blockIdx.x * 128;
    int m0 = blockIdx.y * 128;

    float4 acc[2][8];
    #pragma unroll
    for (int mi = 0; mi < 2; mi++)
        #pragma unroll
        for (int ni = 0; ni < 8; ni++) acc[mi][ni] = make_float4(0.f,0.f,0.f,0.f);

    // loader mapping: 8 cp.async per thread per stage
    int lr = tid >> 2;                  // 0..63
    int u  = (tid & 3) * 8;             // elem offset 0,8,16,24

    const __nv_bfloat16* pAh0 = Ah + (size_t)(m0 + lr)*K + u;
    const __nv_bfloat16* pAh1 = Ah + (size_t)(m0 + lr + 64)*K + u;
    const __nv_bfloat16* pAl0 = Al + (size_t)(m0 + lr)*K + u;
    const __nv_bfloat16* pAl1 = Al + (size_t)(m0 + lr + 64)*K + u;
    const __nv_bfloat16* pBh0 = Bh + (size_t)(n0 + lr)*K + u;
    const __nv_bfloat16* pBh1 = Bh + (size_t)(n0 + lr + 64)*K + u;
    const __nv_bfloat16* pBl0 = Bl + (size_t)(n0 + lr)*K + u;
    const __nv_bfloat16* pBl1 = Bl + (size_t)(n0 + lr + 64)*K + u;
    uint32_t sA0  = (uint32_t)(lr*APADq + u);
    uint32_t sA1  = (uint32_t)((lr+64)*APADq + u);
    uint32_t sAl0 = A_EL + sA0;
    uint32_t sAl1 = A_EL + sA1;
    uint32_t sB0  = 2*A_EL + sA0;
    uint32_t sB1  = 2*A_EL + sA1;
    uint32_t sBl0 = sB0 + B_EL;
    uint32_t sBl1 = sB1 + B_EL;

    int NKB = K / BKq;

    LOADSTAGE(0, 0);

    // ldmatrix lane addressing
    int arow = warp_m*32 + (lane & 15);
    int acol = (lane >> 4) * 8;
    int brow = warp_n*64 + (lane & 7);
    int bcol = ((lane >> 3) & 1) * 8;

    for (int kb = 0; kb < NKB; kb++) {
        if (kb + 1 < NKB) {
            LOADSTAGE((kb + 1) & 1, (kb + 1) * BKq);
            cp_wait<1>();
        } else {
            cp_wait<0>();
        }
        __syncthreads();

        uint32_t base = smb + (uint32_t)((kb & 1) * STG) * 2u;
        uint32_t aH = base;
        uint32_t aL = base + A_EL*2u;
        uint32_t bH = base + 2*A_EL*2u;
        uint32_t bL = bH + B_EL*2u;

        #pragma unroll
        for (int ks = 0; ks < 2; ks++) {
            uint4 ah[2], al[2];
            uint2 bh[8], bl[8];
            #pragma unroll
            for (int mi = 0; mi < 2; mi++) {
                uint32_t off = (uint32_t)((arow + mi*16)*APADq + acol + ks*16) * 2u;
                LDSM4(ah[mi].x, ah[mi].y, ah[mi].z, ah[mi].w, aH + off);
                LDSM4(al[mi].x, al[mi].y, al[mi].z, al[mi].w, aL + off);
            }
            #pragma unroll
            for (int ni = 0; ni < 8; ni++) {
                uint32_t off = (uint32_t)((brow + ni*8)*APADq + bcol + ks*16) * 2u;
                LDSM2(bh[ni].x, bh[ni].y, bH + off);
                LDSM2(bl[ni].x, bl[ni].y, bL + off);
            }
            #pragma unroll
            for (int mi = 0; mi < 2; mi++)
                #pragma unroll
                for (int ni = 0; ni < 8; ni++)
                    MMA3(acc[mi][ni], ah[mi], al[mi], bh[ni], bl[ni]);
        }
        __syncthreads();
    }

    #pragma unroll
    for (int mi = 0; mi < 2; mi++) {
        int r0 = m0 + warp_m*32 + mi*16 + (lane >> 2);
        #pragma unroll
        for (int ni = 0; ni < 8; ni++) {
            int cc = n0 + warp_n*64 + ni*8 + (lane & 3)*2;
            *(float2*)(C + (size_t)r0*1024 + cc)     = make_float2(acc[mi][ni].x, acc[mi][ni].y);
            *(float2*)(C + (size_t)(r0+8)*1024 + cc) = make_float2(acc[mi][ni].z, acc[mi][ni].w);
        }
    }
}

// ---------------- 5) sparse dilated attention (writes split-bf16 out) --------
__global__ void k_attn(const int* __restrict__ positions, int adim) {
    const float* gq = g_qkv;
    const float* gk = g_qkv + (size_t)NT*D_;
    const float* gv = g_qkv + (size_t)2*NT*D_;
    int n = blockIdx.x;
    int b = n / T_, t = n % T_;
    int h = threadIdx.x >> 5;
    int lane = threadIdx.x & 31;

    int cnt = 1 + min(t, 3);
    for (int kk = 4; kk <= t; kk <<= 1) cnt++;

    const float* qr = gq + (size_t)n*D_ + h*DH;
    float2 qv = *(const float2*)(qr + lane*2);

    int pos[AMAX];
    float sc[AMAX];
    #pragma unroll
    for (int a = 0; a < AMAX; a++) {
        if (a < cnt) {
            pos[a] = positions[t*adim + a];
            const float* kr = gk + (size_t)(b*T_ + pos[a])*D_ + h*DH;
            float2 kv = *(const float2*)(kr + lane*2);
            float s = qv.x*kv.x + qv.y*kv.y;
            #pragma unroll
            for (int off = 16; off; off >>= 1) s += __shfl_xor_sync(~0u, s, off);
            sc[a] = s * 0.125f;
        } else { pos[a] = 0; sc[a] = NEGF; }
    }
    float m = NEGF;
    #pragma unroll
    for (int a = 0; a < AMAX; a++) m = fmaxf(m, sc[a]);
    float sum = 0.f;
    #pragma unroll
    for (int a = 0; a < AMAX; a++) {
        sc[a] = (a < cnt) ? expf(sc[a] - m) : 0.f;
        sum += sc[a];
    }
    float inv = 1.f / sum;
    float2 acc = make_float2(0.f, 0.f);
    #pragma unroll
    for (int a = 0; a < AMAX; a++) {
        if (a < cnt) {
            const float* vr = gv + (size_t)(b*T_ + pos[a])*D_ + h*DH;
            float2 vv = *(const float2*)(vr + lane*2);
            float w = sc[a]*inv;
            acc.x += w*vv.x; acc.y += w*vv.y;
        }
    }
    size_t oidx = (size_t)n*D_ + h*DH + lane*2;
    split_bf(acc.x, g_Abh, g_Abl, oidx);
    split_bf(acc.y, g_Abh, g_Abl, oidx + 1);
}

// ---------------- launch ------------------------------------------------------
// Only harness pointers and plain ints cross the host->kernel boundary.
extern "C" void kernel_launch(void* const* d_in, const int* in_sizes, int n_in,
                              void* d_out, int out_size) {
    const float* x      = (const float*)d_in[0];
    const float* Wp     = (const float*)d_in[1];
    const float* Wi     = (const float*)d_in[2];
    const float* Wd     = (const float*)d_in[3];
    const float* gate_w = (const float*)d_in[4];
    const float* gate_b = (const float*)d_in[5];
    const float* kick_v = (const float*)d_in[6];
    const float* kick_w = (const float*)d_in[7];
    const float* kick_b = (const float*)d_in[8];
    const float* o_w    = (const float*)d_in[9];
    const int* positions = (const int*)d_in[10];
    int adim = in_sizes[10] / T_;

    cudaFuncSetAttribute(k_gemm, cudaFuncAttributeMaxDynamicSharedMemorySize, GEMM_SMEM);

    k_stats<<<NT, 256>>>(x, gate_w, gate_b, kick_w, kick_b);
    k_scan1<<<dim3(D_/256, CH, B_), 256>>>(x);
    k_scan2<<<dim3(D_/256, B_), 256>>>();

    k_buildA<<<NT, 256>>>(x, kick_v);              // all 3 projections
    k_buildB<<<3*D_, 256>>>(Wp, Wi, Wd);           // all 3 projections

    // q,k,v: one batched GEMM, gridDim.z = projection (M=4096, N=1024, K'=3072)
    k_gemm<<<dim3(D_/128, NT/128, 3), 256, GEMM_SMEM>>>(nullptr, 3*D_, 0);

    k_attn<<<NT, 512>>>(positions, adim);          // writes split-bf16 into g_Ab*
    k_split_ow<<<(D_*D_)/256, 256>>>(o_w, D_*D_);

    // out = attn @ o_w^T  (M=4096, N=1024, K=1024)
    k_gemm<<<dim3(D_/128, NT/128, 1), 256, GEMM_SMEM>>>((float*)d_out, D_, 1);
}

// round 17
// speedup vs baseline: 1.0731x; 1.0078x over previous
#include <cuda_runtime.h>
#include <cuda_bf16.h>
#include <cstdint>

#define B_ 2
#define T_ 2048
#define D_ 1024
#define NT (B_*T_)          // 4096
#define NH 16
#define DH 64
#define AMAX 15
#define NEGF (-1e30f)
#define CH 16               // scan chunks
#define CL (T_/CH)          // 128
#define LOG2_095 (-0.07400058003f)   // log2(0.95)
#define P128 (0.0014080610f)         // 0.95^128

// ---------------- scratch (device-side only; NEVER passed from host) ---------
__device__ float g_gates[NT*9];
__device__ float g_kick[NT*3];
__device__ float g_Ilocal[(size_t)NT*D_];
__device__ float g_cend[B_*CH*D_];
__device__ float g_cin[B_*CH*D_];
__device__ __nv_bfloat16 g_Abh[(size_t)3*NT*3*D_];  // A hi, all 3 projections (also attn-out)
__device__ __nv_bfloat16 g_Abl[(size_t)3*NT*3*D_];  // A lo
__device__ __nv_bfloat16 g_Bbh[(size_t)3*D_*3*D_];  // B hi, all 3 projections (also o_w)
__device__ __nv_bfloat16 g_Bbl[(size_t)3*D_*3*D_];  // B lo
__device__ float g_qkv[(size_t)3*NT*D_];            // q,k,v

// ---------------- PTX helpers ------------------------------------------------
__device__ __forceinline__ uint32_t cvta_smem(const void* p){
    uint32_t a;
    asm("{ .reg .u64 t; cvta.to.shared.u64 t, %1; cvt.u32.u64 %0, t; }":"=r"(a):"l"(p));
    return a;
}
__device__ __forceinline__ void cpasync16(uint32_t dst, const void* src){
    asm volatile("cp.async.cg.shared.global [%0],[%1],16;"::"r"(dst),"l"(src));
}
__device__ __forceinline__ void cp_commit(){ asm volatile("cp.async.commit_group;":::"memory"); }
template<int N> __device__ __forceinline__ void cp_wait(){
    asm volatile("cp.async.wait_group %0;"::"n"(N):"memory");
}
#define LDSM4(r0,r1,r2,r3,addr) \
    asm volatile("ldmatrix.sync.aligned.m8n8.x4.shared.b16 {%0,%1,%2,%3}, [%4];" \
        : "=r"(r0),"=r"(r1),"=r"(r2),"=r"(r3) : "r"(addr))
#define LDSM2(r0,r1,addr) \
    asm volatile("ldmatrix.sync.aligned.m8n8.x2.shared.b16 {%0,%1}, [%2];" \
        : "=r"(r0),"=r"(r1) : "r"(addr))
#define MMA16816(c0,c1,c2,c3,a0,a1,a2,a3,b0,b1) \
    asm volatile("mma.sync.aligned.m16n8k16.row.col.f32.bf16.bf16.f32 " \
        "{%0,%1,%2,%3}, {%4,%5,%6,%7}, {%8,%9}, {%0,%1,%2,%3};" \
        : "+f"(c0),"+f"(c1),"+f"(c2),"+f"(c3) \
        : "r"(a0),"r"(a1),"r"(a2),"r"(a3),"r"(b0),"r"(b1))
// 3-term split product: ah*bh + ah*bl + al*bh
#define MMA3(c, ah_, al_, bh_, bl_) do { \
    MMA16816(c.x,c.y,c.z,c.w, ah_.x,ah_.y,ah_.z,ah_.w, bh_.x,bh_.y); \
    MMA16816(c.x,c.y,c.z,c.w, ah_.x,ah_.y,ah_.z,ah_.w, bl_.x,bl_.y); \
    MMA16816(c.x,c.y,c.z,c.w, al_.x,al_.y,al_.z,al_.w, bh_.x,bh_.y); \
} while(0)

// ---------------- 1) per-token stats -----------------------------------------
__global__ void k_stats(const float* __restrict__ x,
                        const float* __restrict__ gate_w,
                        const float* __restrict__ gate_b,
                        const float* __restrict__ kick_w,
                        const float* __restrict__ kick_b) {
    int n = blockIdx.x;
    int t = n % T_;
    int tid = threadIdx.x;
    const float* xr = x + (size_t)n * D_;
    const float* xp = xr - D_;

    float s[15];
    #pragma unroll
    for (int i = 0; i < 15; i++) s[i] = 0.f;
    for (int d = tid; d < D_; d += 256) {
        float xv = xr[d];
        float pv = (t > 0) ? xp[d] : 0.f;
        s[0] += xv * xv; s[1] += pv * pv; s[2] += xv * pv;
        #pragma unroll
        for (int j = 0; j < 9; j++) s[3 + j] += xv * gate_w[j * D_ + d];
        #pragma unroll
        for (int p = 0; p < 3; p++) s[12 + p] += xv * kick_w[p * D_ + d];
    }
    #pragma unroll
    for (int i = 0; i < 15; i++)
        for (int off = 16; off; off >>= 1) s[i] += __shfl_xor_sync(~0u, s[i], off);

    __shared__ float red[8][15];
    int w = tid >> 5, l = tid & 31;
    if (l == 0) {
        #pragma unroll
        for (int i = 0; i < 15; i++) red[w][i] = s[i];
    }
    __syncthreads();
    if (tid == 0) {
        float f[15];
        #pragma unroll
        for (int i = 0; i < 15; i++) {
            float a = 0.f;
            #pragma unroll
            for (int w2 = 0; w2 < 8; w2++) a += red[w2][i];
            f[i] = a;
        }
        float n1 = fmaxf(sqrtf(f[0]), 1e-12f);
        float n2 = fmaxf(sqrtf(f[1]), 1e-12f);
        float cosv = (t > 0) ? f[2] / (n1 * n2) : 0.f;
        float stag = (cosv > 0.95f) ? 1.f : 0.f;
        #pragma unroll
        for (int p = 0; p < 3; p++) {
            float l0 = f[3+p*3+0] + gate_b[p*3+0];
            float l1 = f[3+p*3+1] + gate_b[p*3+1];
            float l2 = f[3+p*3+2] + gate_b[p*3+2];
            float m = fmaxf(l0, fmaxf(l1, l2));
            float e0 = expf(l0-m), e1 = expf(l1-m), e2 = expf(l2-m);
            float inv = 1.f / (e0+e1+e2);
            float g0 = fminf(e0*inv, 0.6f);
            float g1 = fmaxf(fminf(e1*inv, 0.6f), 0.25f);
            float g2 = fminf(e2*inv, 0.6f);
            float inv2 = 1.f / (g0+g1+g2);
            g_gates[n*9+p*3+0] = g0*inv2;
            g_gates[n*9+p*3+1] = g1*inv2;
            g_gates[n*9+p*3+2] = g2*inv2;
            float ks = 1.f / (1.f + expf(-(f[12+p] + kick_b[p])));
            g_kick[n*3+p] = stag * ks;
        }
    }
}

// ---------------- 2) chunked EMA scan ----------------------------------------
__global__ void k_scan1(const float* __restrict__ x) {
    int d = blockIdx.x * 256 + threadIdx.x;
    int c = blockIdx.y, b = blockIdx.z;
    const float* xb = x + ((size_t)(b*T_ + c*CL))*D_ + d;
    float* Ib = g_Ilocal + ((size_t)(b*T_ + c*CL))*D_ + d;
    float L; int t0;
    if (c == 0) { L = xb[0]; Ib[0] = L; t0 = 1; }
    else { L = 0.f; t0 = 0; }
    for (int t = t0; t < CL; t++) {
        L = 0.95f*L + 0.05f*xb[(size_t)t*D_];
        Ib[(size_t)t*D_] = L;
    }
    g_cend[(b*CH + c)*D_ + d] = L;
}

__global__ void k_scan2() {
    int d = blockIdx.x * 256 + threadIdx.x;
    int b = blockIdx.y;
    float I = g_cend[(b*CH + 0)*D_ + d];
    g_cin[(b*CH + 0)*D_ + d] = 0.f;
    for (int c = 1; c < CH; c++) {
        g_cin[(b*CH + c)*D_ + d] = I;
        I = g_cend[(b*CH + c)*D_ + d] + P128 * I;
    }
}

// ---------------- 3) split-bf16 operand builders ------------------------------
__device__ __forceinline__ void split_bf(float v, __nv_bfloat16* H, __nv_bfloat16* L, size_t i){
    __nv_bfloat16 h = __float2bfloat16_rn(v);
    H[i] = h;
    L[i] = __float2bfloat16_rn(v - __bfloat162float(h));
}

// A'' for ALL projections: [p][n][ g0*x | g1*I | g2*(dx + kick*kick_v) ]
__global__ void k_buildA(const float* __restrict__ x, const float* __restrict__ kick_v) {
    int n = blockIdx.x;
    int b = n / T_, t = n % T_;
    int c = t / CL;
    float pfac = exp2f((float)((t % CL) + 1) * LOG2_095);   // 0.95^(tm+1)
    __shared__ float gg[9], kk[3];
    if (threadIdx.x < 9) gg[threadIdx.x] = g_gates[n*9 + threadIdx.x];
    if (threadIdx.x < 3) kk[threadIdx.x] = g_kick[n*3 + threadIdx.x];
    __syncthreads();
    for (int d = threadIdx.x; d < D_; d += 256) {
        float xv = x[(size_t)n*D_ + d];
        float dv = (t > 0) ? (xv - x[(size_t)(n-1)*D_ + d]) : 0.f;
        float Iv = g_Ilocal[(size_t)n*D_ + d] + pfac * g_cin[(b*CH + c)*D_ + d];
        #pragma unroll
        for (int p = 0; p < 3; p++) {
            size_t base = ((size_t)p*NT + n) * (3*D_);
            split_bf(gg[p*3+0]*xv, g_Abh, g_Abl, base + d);
            split_bf(gg[p*3+1]*Iv, g_Abh, g_Abl, base + D_ + d);
            split_bf(gg[p*3+2]*(dv + kk[p]*kick_v[p*D_ + d]), g_Abh, g_Abl, base + 2*D_ + d);
        }
    }
}

// B'' for ALL projections: global row (p*1024+o) = [ Wp_p[o] | Wi_p[o] | Wd_p[o] ]
__global__ void k_buildB(const float* __restrict__ Wp, const float* __restrict__ Wi,
                         const float* __restrict__ Wd) {
    int row = blockIdx.x;                    // 0..3*D_-1
    size_t base = (size_t)row * (3*D_);
    size_t wsrc = (size_t)row * D_;
    for (int d = threadIdx.x; d < D_; d += 256) {
        split_bf(Wp[wsrc + d], g_Bbh, g_Bbl, base + d);
        split_bf(Wi[wsrc + d], g_Bbh, g_Bbl, base + D_ + d);
        split_bf(Wd[wsrc + d], g_Bbh, g_Bbl, base + 2*D_ + d);
    }
}

// split o_w into the start of the B buffers (after projection GEMMs are done)
__global__ void k_split_ow(const float* __restrict__ src, int nElem) {
    int i = blockIdx.x * 256 + threadIdx.x;
    if (i < nElem) split_bf(src[i], g_Bbh, g_Bbl, i);
}

// ---------------- 4) bf16 mma.sync GEMM — 128x128 tile, 2-stage, 2 CTA/SM ----
// 8 warps (4x2), warp tile 32x64. C = Ah*Bh^T + Ah*Bl^T + Al*Bh^T, fp32 acc.
// blockIdx.z = projection p: A base = p*NT*K, B base = p*D_*K; ldc = 1024.
#define BKq 32
#define APADq 40                        // 80 B rows: conflict-free ldmatrix banking
#define A_EL (128*APADq)                // 5120 elems (A: 128 rows)
#define B_EL (128*APADq)                // 5120 elems (B: 128 rows)
#define STG (2*A_EL + 2*B_EL)           // 20480 elems (40960 B) per stage
#define GEMM_SMEM (2*STG*2)             // 81920 B, 2 stages → 2 CTAs/SM

#define LOADSTAGE(st, ko) do { \
    uint32_t so_ = (uint32_t)(st) * STG; \
    cpasync16(smb + (so_ + sA0)*2u,  pAh0 + (ko)); \
    cpasync16(smb + (so_ + sA1)*2u,  pAh1 + (ko)); \
    cpasync16(smb + (so_ + sAl0)*2u, pAl0 + (ko)); \
    cpasync16(smb + (so_ + sAl1)*2u, pAl1 + (ko)); \
    cpasync16(smb + (so_ + sB0)*2u,  pBh0 + (ko)); \
    cpasync16(smb + (so_ + sB1)*2u,  pBh1 + (ko)); \
    cpasync16(smb + (so_ + sBl0)*2u, pBl0 + (ko)); \
    cpasync16(smb + (so_ + sBl1)*2u, pBl1 + (ko)); \
    cp_commit(); \
} while(0)

__global__ void __launch_bounds__(256,2) k_gemm(float* __restrict__ Cext,
                                                int K, int useExt)
{
    int z = blockIdx.z;
    const __nv_bfloat16* Ah = g_Abh + (size_t)z*NT*K;
    const __nv_bfloat16* Al = g_Abl + (size_t)z*NT*K;
    const __nv_bfloat16* Bh = g_Bbh + (size_t)z*D_*K;
    const __nv_bfloat16* Bl = g_Bbl + (size_t)z*D_*K;
    float* C = useExt ? Cext : (g_qkv + (size_t)z*NT*D_);

    extern __shared__ __align__(16) __nv_bfloat16 smarr[];
    uint32_t smb = cvta_smem(smarr);
    int tid = threadIdx.x, lane = tid & 31, wid = tid >> 5;
    int warp_m = wid >> 1, warp_n = wid & 1;      // 4 x 2 warps; warp tile 32x64
    int n0 = blockIdx.x * 128;
    int m0 = blockIdx.y * 128;

    float4 acc[2][8];
    #pragma unroll
    for (int mi = 0; mi < 2; mi++)
        #pragma unroll
        for (int ni = 0; ni < 8; ni++) acc[mi][ni] = make_float4(0.f,0.f,0.f,0.f);

    // loader mapping: 8 cp.async per thread per stage
    int lr = tid >> 2;                  // 0..63
    int u  = (tid & 3) * 8;             // elem offset 0,8,16,24

    const __nv_bfloat16* pAh0 = Ah + (size_t)(m0 + lr)*K + u;
    const __nv_bfloat16* pAh1 = Ah + (size_t)(m0 + lr + 64)*K + u;
    const __nv_bfloat16* pAl0 = Al + (size_t)(m0 + lr)*K + u;
    const __nv_bfloat16* pAl1 = Al + (size_t)(m0 + lr + 64)*K + u;
    const __nv_bfloat16* pBh0 = Bh + (size_t)(n0 + lr)*K + u;
    const __nv_bfloat16* pBh1 = Bh + (size_t)(n0 + lr + 64)*K + u;
    const __nv_bfloat16* pBl0 = Bl + (size_t)(n0 + lr)*K + u;
    const __nv_bfloat16* pBl1 = Bl + (size_t)(n0 + lr + 64)*K + u;
    uint32_t sA0  = (uint32_t)(lr*APADq + u);
    uint32_t sA1  = (uint32_t)((lr+64)*APADq + u);
    uint32_t sAl0 = A_EL + sA0;
    uint32_t sAl1 = A_EL + sA1;
    uint32_t sB0  = 2*A_EL + sA0;
    uint32_t sB1  = 2*A_EL + sA1;
    uint32_t sBl0 = sB0 + B_EL;
    uint32_t sBl1 = sB1 + B_EL;

    int NKB = K / BKq;

    LOADSTAGE(0, 0);

    // ldmatrix lane addressing
    int arow = warp_m*32 + (lane & 15);
    int acol = (lane >> 4) * 8;
    int brow = warp_n*64 + (lane & 7);
    int bcol = ((lane >> 3) & 1) * 8;

    for (int kb = 0; kb < NKB; kb++) {
        if (kb + 1 < NKB) {
            LOADSTAGE((kb + 1) & 1, (kb + 1) * BKq);
            cp_wait<1>();
        } else {
            cp_wait<0>();
        }
        __syncthreads();

        uint32_t base = smb + (uint32_t)((kb & 1) * STG) * 2u;
        uint32_t aH = base;
        uint32_t aL = base + A_EL*2u;
        uint32_t bH = base + 2*A_EL*2u;
        uint32_t bL = bH + B_EL*2u;

        #pragma unroll
        for (int ks = 0; ks < 2; ks++) {
            uint4 ah[2], al[2];
            uint2 bh[8], bl[8];
            #pragma unroll
            for (int mi = 0; mi < 2; mi++) {
                uint32_t off = (uint32_t)((arow + mi*16)*APADq + acol + ks*16) * 2u;
                LDSM4(ah[mi].x, ah[mi].y, ah[mi].z, ah[mi].w, aH + off);
                LDSM4(al[mi].x, al[mi].y, al[mi].z, al[mi].w, aL + off);
            }
            #pragma unroll
            for (int ni = 0; ni < 8; ni++) {
                uint32_t off = (uint32_t)((brow + ni*8)*APADq + bcol + ks*16) * 2u;
                LDSM2(bh[ni].x, bh[ni].y, bH + off);
                LDSM2(bl[ni].x, bl[ni].y, bL + off);
            }
            #pragma unroll
            for (int mi = 0; mi < 2; mi++)
                #pragma unroll
                for (int ni = 0; ni < 8; ni++)
                    MMA3(acc[mi][ni], ah[mi], al[mi], bh[ni], bl[ni]);
        }
        __syncthreads();
    }

    #pragma unroll
    for (int mi = 0; mi < 2; mi++) {
        int r0 = m0 + warp_m*32 + mi*16 + (lane >> 2);
        #pragma unroll
        for (int ni = 0; ni < 8; ni++) {
            int cc = n0 + warp_n*64 + ni*8 + (lane & 3)*2;
            *(float2*)(C + (size_t)r0*1024 + cc)     = make_float2(acc[mi][ni].x, acc[mi][ni].y);
            *(float2*)(C + (size_t)(r0+8)*1024 + cc) = make_float2(acc[mi][ni].z, acc[mi][ni].w);
        }
    }
}

// ---------------- 5) sparse dilated attention (writes split-bf16 out) --------
__global__ void k_attn(const int* __restrict__ positions, int adim) {
    const float* gq = g_qkv;
    const float* gk = g_qkv + (size_t)NT*D_;
    const float* gv = g_qkv + (size_t)2*NT*D_;
    int n = blockIdx.x;
    int b = n / T_, t = n % T_;
    int h = threadIdx.x >> 5;
    int lane = threadIdx.x & 31;

    int cnt = 1 + min(t, 3);
    for (int kk = 4; kk <= t; kk <<= 1) cnt++;

    const float* qr = gq + (size_t)n*D_ + h*DH;
    float2 qv = *(const float2*)(qr + lane*2);

    int pos[AMAX];
    float sc[AMAX];
    #pragma unroll
    for (int a = 0; a < AMAX; a++) {
        if (a < cnt) {
            pos[a] = positions[t*adim + a];
            const float* kr = gk + (size_t)(b*T_ + pos[a])*D_ + h*DH;
            float2 kv = *(const float2*)(kr + lane*2);
            float s = qv.x*kv.x + qv.y*kv.y;
            #pragma unroll
            for (int off = 16; off; off >>= 1) s += __shfl_xor_sync(~0u, s, off);
            sc[a] = s * 0.125f;
        } else { pos[a] = 0; sc[a] = NEGF; }
    }
    float m = NEGF;
    #pragma unroll
    for (int a = 0; a < AMAX; a++) m = fmaxf(m, sc[a]);
    float sum = 0.f;
    #pragma unroll
    for (int a = 0; a < AMAX; a++) {
        sc[a] = (a < cnt) ? expf(sc[a] - m) : 0.f;
        sum += sc[a];
    }
    float inv = 1.f / sum;
    float2 acc = make_float2(0.f, 0.f);
    #pragma unroll
    for (int a = 0; a < AMAX; a++) {
        if (a < cnt) {
            const float* vr = gv + (size_t)(b*T_ + pos[a])*D_ + h*DH;
            float2 vv = *(const float2*)(vr + lane*2);
            float w = sc[a]*inv;
            acc.x += w*vv.x; acc.y += w*vv.y;
        }
    }
    size_t oidx = (size_t)n*D_ + h*DH + lane*2;
    split_bf(acc.x, g_Abh, g_Abl, oidx);
    split_bf(acc.y, g_Abh, g_Abl, oidx + 1);
}

// ---------------- launch ------------------------------------------------------
// Only harness pointers and plain ints cross the host->kernel boundary.
extern "C" void kernel_launch(void* const* d_in, const int* in_sizes, int n_in,
                              void* d_out, int out_size) {
    const float* x      = (const float*)d_in[0];
    const float* Wp     = (const float*)d_in[1];
    const float* Wi     = (const float*)d_in[2];
    const float* Wd     = (const float*)d_in[3];
    const float* gate_w = (const float*)d_in[4];
    const float* gate_b = (const float*)d_in[5];
    const float* kick_v = (const float*)d_in[6];
    const float* kick_w = (const float*)d_in[7];
    const float* kick_b = (const float*)d_in[8];
    const float* o_w    = (const float*)d_in[9];
    const int* positions = (const int*)d_in[10];
    int adim = in_sizes[10] / T_;

    cudaFuncSetAttribute(k_gemm, cudaFuncAttributeMaxDynamicSharedMemorySize, GEMM_SMEM);

    k_stats<<<NT, 256>>>(x, gate_w, gate_b, kick_w, kick_b);
    k_scan1<<<dim3(D_/256, CH, B_), 256>>>(x);
    k_scan2<<<dim3(D_/256, B_), 256>>>();

    k_buildA<<<NT, 256>>>(x, kick_v);              // all 3 projections
    k_buildB<<<3*D_, 256>>>(Wp, Wi, Wd);           // all 3 projections

    // q,k,v: one batched GEMM, gridDim.z = projection (M=4096, N=1024, K'=3072)
    k_gemm<<<dim3(D_/128, NT/128, 3), 256, GEMM_SMEM>>>(nullptr, 3*D_, 0);

    k_attn<<<NT, 512>>>(positions, adim);          // writes split-bf16 into g_Ab*
    k_split_ow<<<(D_*D_)/256, 256>>>(o_w, D_*D_);

    // out = attn @ o_w^T  (M=4096, N=1024, K=1024)
    k_gemm<<<dim3(D_/128, NT/128, 1), 256, GEMM_SMEM>>>((float*)d_out, D_, 1);
}